// round 5
// baseline (speedup 1.0000x reference)
#include <cuda_runtime.h>
#include <cstdint>
#include <math.h>

#define NB 64
#define LOOKBACK 32
#define NS 256
#define DM 512
#define DK 128
#define DV 128
#define WST 4                  // stocks per warp in main kernel
#define CPB (NS / (4 * WST))   // CTAs per batch in main = 16
#define NPART CPB              // 16 CTA-partials per batch

// ---- scratch (device globals: allocation-free) ----
__device__ float  g_u[NB * DM];             // u[b,d] = (q[b] @ W_k)[d] / sqrt(DK)
__device__ float4 g_stock[NS];              // {alpha, gate, lag_floor, lag_ceil}
__device__ float  g_pctx[NB * NPART * DM];  // CTA partial contexts (unnormalized)
__device__ float  g_m[NB * NPART];          // CTA running max
__device__ float  g_l[NB * NPART];          // CTA running sum

__device__ __forceinline__ float sigmoidf_(float x) {
    return 1.0f / (1.0f + __expf(-x));
}

__device__ __forceinline__ void cp16(void* smem_dst, const void* gmem_src) {
    unsigned int d = (unsigned int)__cvta_generic_to_shared(smem_dst);
    asm volatile("cp.async.cg.shared.global [%0], [%1], 16;\n" :: "r"(d), "l"(gmem_src));
}
__device__ __forceinline__ void cp_commit() {
    asm volatile("cp.async.commit_group;\n");
}
template <int N>
__device__ __forceinline__ void cp_wait() {
    asm volatile("cp.async.wait_group %0;\n" :: "n"(N));
}

// ============================================================================
// Kernel 1: prep. One CTA per batch (64 CTAs x 512 threads).
// ============================================================================
__global__ __launch_bounds__(512) void prep_kernel(
    const float* __restrict__ query,
    const float* __restrict__ Wq,
    const float* __restrict__ Wk,
    const float* __restrict__ lags,
    const float* __restrict__ gates,
    const void*  __restrict__ mlraw)
{
    __shared__ float  qs[DM];
    __shared__ float  qk[DK];
    __shared__ float4 sred[4][DM / 4];   // stage-B partial sums, 8 KB

    const int tid = threadIdx.x;    // 0..511
    const int b   = blockIdx.x;

    // per-stock meta (block 0 only)
    if (b == 0 && tid < NS) {
        float ml = 16.0f;
        if (mlraw != nullptr) {
            int   iv = ((const int*)mlraw)[0];
            float fv = ((const float*)mlraw)[0];
            ml = (iv > 0 && iv <= 65536) ? (float)iv : fv;
        }
        float lag = sigmoidf_(lags[tid]) * ml;
        int ifl = min(max((int)floorf(lag), 0), LOOKBACK - 1);
        int icl = min(max((int)ceilf(lag),  0), LOOKBACK - 1);
        float alpha = lag - (float)ifl;
        float gate  = sigmoidf_(gates[tid]);
        g_stock[tid] = make_float4(alpha, gate, (float)ifl, (float)icl);
    }

    qs[tid] = query[(size_t)b * DM + tid];
    __syncthreads();

    // ---- stage A: q[b,k] = sum_d query[b,d] * Wq[k,d] ----
    const int wid  = tid >> 5;
    const int lane = tid & 31;
    #pragma unroll
    for (int j = 0; j < 8; j++) {
        const int k = j * 16 + wid;
        float acc = 0.f;
        #pragma unroll
        for (int i = 0; i < 16; i++)
            acc = fmaf(Wq[(size_t)k * DM + i * 32 + lane], qs[i * 32 + lane], acc);
        #pragma unroll
        for (int off = 16; off; off >>= 1)
            acc += __shfl_xor_sync(0xffffffffu, acc, off);
        if (lane == 0) qk[k] = acc;
    }
    __syncthreads();

    // ---- stage B: u[b,d] = sum_k q[b,k] * Wk[k,d], K split 4 ways ----
    const int g = tid >> 7;        // 0..3
    const int t = tid & 127;       // 0..127
    float4 acc0 = make_float4(0.f, 0.f, 0.f, 0.f);
    float4 acc1 = acc0;
    const float4* wkb = (const float4*)Wk + (size_t)(g * 32) * (DM / 4) + t;
    #pragma unroll 8
    for (int k = 0; k < 32; k += 2) {
        const float  s0 = qk[g * 32 + k];
        const float  s1 = qk[g * 32 + k + 1];
        const float4 w0 = wkb[(size_t)k * (DM / 4)];
        const float4 w1 = wkb[(size_t)(k + 1) * (DM / 4)];
        acc0.x = fmaf(s0, w0.x, acc0.x); acc0.y = fmaf(s0, w0.y, acc0.y);
        acc0.z = fmaf(s0, w0.z, acc0.z); acc0.w = fmaf(s0, w0.w, acc0.w);
        acc1.x = fmaf(s1, w1.x, acc1.x); acc1.y = fmaf(s1, w1.y, acc1.y);
        acc1.z = fmaf(s1, w1.z, acc1.z); acc1.w = fmaf(s1, w1.w, acc1.w);
    }
    acc0.x += acc1.x; acc0.y += acc1.y; acc0.z += acc1.z; acc0.w += acc1.w;
    sred[g][t] = acc0;
    __syncthreads();

    if (tid < 128) {
        const float inv = 0.08838834764831845f;  // 1/sqrt(128)
        float4 s0 = sred[0][tid], s1 = sred[1][tid], s2 = sred[2][tid], s3 = sred[3][tid];
        float4 r;
        r.x = ((s0.x + s1.x) + (s2.x + s3.x)) * inv;
        r.y = ((s0.y + s1.y) + (s2.y + s3.y)) * inv;
        r.z = ((s0.z + s1.z) + (s2.z + s3.z)) * inv;
        r.w = ((s0.w + s1.w) + (s2.w + s3.w)) * inv;
        ((float4*)g_u)[(size_t)b * (DM / 4) + tid] = r;
    }
}

// ============================================================================
// Kernel 2: main. cp.async double-buffered, warp-autonomous online softmax.
// grid = (CPB, NB), 128 threads. Warp owns WST=4 stocks; lane owns 4 dims x4.
// Stage buffer: [stage][warp][f/c row][128 float4]  (32 KB, reused for combine)
// ============================================================================
__global__ __launch_bounds__(128) void main_kernel(const float* __restrict__ embs)
{
    __shared__ float4 buf[2][4][2][DM / 4];   // 32 KB
    __shared__ float  sml[4][2];

    const int tid  = threadIdx.x;
    const int lane = tid & 31;
    const int wid  = tid >> 5;
    const int b    = blockIdx.y;
    const int s0   = (blockIdx.x * 4 + wid) * WST;

    const float4* base = (const float4*)embs + (size_t)b * LOOKBACK * NS * (DM / 4);
    const float4* ub   = (const float4*)g_u  + (size_t)b * (DM / 4);
    const float4 u0 = __ldg(ub + lane),      u1 = __ldg(ub + 32 + lane);
    const float4 u2 = __ldg(ub + 64 + lane), u3 = __ldg(ub + 96 + lane);

    // issue stock i into stage (i & 1)
    auto issue = [&](int i) {
        const int s = s0 + i;
        const float4 mt = g_stock[s];
        const float4* rf = base + ((int)mt.z * NS + s) * (DM / 4);
        const float4* rc = base + ((int)mt.w * NS + s) * (DM / 4);
        float4* df = &buf[i & 1][wid][0][0];
        float4* dc = &buf[i & 1][wid][1][0];
        #pragma unroll
        for (int r = 0; r < 4; r++) {
            cp16(df + r * 32 + lane, rf + r * 32 + lane);
            cp16(dc + r * 32 + lane, rc + r * 32 + lane);
        }
        cp_commit();
    };

    issue(0);
    issue(1);

    float  m = -INFINITY, l = 0.f;
    float4 x0 = make_float4(0.f,0.f,0.f,0.f), x1 = x0, x2 = x0, x3 = x0;

    #pragma unroll
    for (int i = 0; i < WST; i++) {
        if (i < WST - 1) cp_wait<1>(); else cp_wait<0>();

        // read this lane's own staged data (written by this lane)
        const float4* df = &buf[i & 1][wid][0][0];
        const float4* dc = &buf[i & 1][wid][1][0];
        float4 f0 = df[lane], f1 = df[32+lane], f2 = df[64+lane], f3 = df[96+lane];
        float4 c0 = dc[lane], c1 = dc[32+lane], c2 = dc[64+lane], c3 = dc[96+lane];

        // refill this stage with stock i+2 (safe: we've consumed into regs)
        if (i + 2 < WST) issue(i + 2);

        const float4 mt = g_stock[s0 + i];
        const float a = mt.x, gt = mt.y, oma = 1.0f - mt.x;

        f0.x = oma*f0.x + a*c0.x; f0.y = oma*f0.y + a*c0.y; f0.z = oma*f0.z + a*c0.z; f0.w = oma*f0.w + a*c0.w;
        f1.x = oma*f1.x + a*c1.x; f1.y = oma*f1.y + a*c1.y; f1.z = oma*f1.z + a*c1.z; f1.w = oma*f1.w + a*c1.w;
        f2.x = oma*f2.x + a*c2.x; f2.y = oma*f2.y + a*c2.y; f2.z = oma*f2.z + a*c2.z; f2.w = oma*f2.w + a*c2.w;
        f3.x = oma*f3.x + a*c3.x; f3.y = oma*f3.y + a*c3.y; f3.z = oma*f3.z + a*c3.z; f3.w = oma*f3.w + a*c3.w;

        float p0 = f0.x*u0.x + f0.y*u0.y + f0.z*u0.z + f0.w*u0.w;
        float p1 = f1.x*u1.x + f1.y*u1.y + f1.z*u1.z + f1.w*u1.w;
        float p2 = f2.x*u2.x + f2.y*u2.y + f2.z*u2.z + f2.w*u2.w;
        float p3 = f3.x*u3.x + f3.y*u3.y + f3.z*u3.z + f3.w*u3.w;
        float part = (p0 + p1) + (p2 + p3);
        #pragma unroll
        for (int off = 16; off; off >>= 1)
            part += __shfl_xor_sync(0xffffffffu, part, off);
        const float score = part * gt;   // 1/sqrt(dk) folded into u

        const float mnew = fmaxf(m, score);
        const float corr = __expf(m - mnew);
        const float p    = __expf(score - mnew);
        l = l * corr + p;
        x0.x = x0.x*corr + p*f0.x; x0.y = x0.y*corr + p*f0.y; x0.z = x0.z*corr + p*f0.z; x0.w = x0.w*corr + p*f0.w;
        x1.x = x1.x*corr + p*f1.x; x1.y = x1.y*corr + p*f1.y; x1.z = x1.z*corr + p*f1.z; x1.w = x1.w*corr + p*f1.w;
        x2.x = x2.x*corr + p*f2.x; x2.y = x2.y*corr + p*f2.y; x2.z = x2.z*corr + p*f2.z; x2.w = x2.w*corr + p*f2.w;
        x3.x = x3.x*corr + p*f3.x; x3.y = x3.y*corr + p*f3.y; x3.z = x3.z*corr + p*f3.z; x3.w = x3.w*corr + p*f3.w;
        m = mnew;
    }

    // ---- CTA combine of 4 warp partials (reuse buf as scratch) ----
    __syncthreads();   // all pipeline reads done; safe to repurpose buf
    float4* sctx = &buf[0][0][0][0];     // 4 warps x 128 float4 = 8 KB
    if (lane == 0) { sml[wid][0] = m; sml[wid][1] = l; }
    sctx[wid * 128 + lane]      = x0;
    sctx[wid * 128 + 32 + lane] = x1;
    sctx[wid * 128 + 64 + lane] = x2;
    sctx[wid * 128 + 96 + lane] = x3;
    __syncthreads();

    const float m0 = sml[0][0], m1 = sml[1][0], m2 = sml[2][0], m3 = sml[3][0];
    const float mg = fmaxf(fmaxf(m0, m1), fmaxf(m2, m3));
    const float w0 = __expf(m0 - mg), w1 = __expf(m1 - mg);
    const float w2 = __expf(m2 - mg), w3 = __expf(m3 - mg);

    const int idx = b * CPB + blockIdx.x;
    if (tid == 0) {
        g_m[idx] = mg;
        g_l[idx] = w0 * sml[0][1] + w1 * sml[1][1] + w2 * sml[2][1] + w3 * sml[3][1];
    }
    const float4 a0 = sctx[tid], a1 = sctx[128 + tid], a2 = sctx[256 + tid], a3 = sctx[384 + tid];
    float4 comb;
    comb.x = w0*a0.x + w1*a1.x + w2*a2.x + w3*a3.x;
    comb.y = w0*a0.y + w1*a1.y + w2*a2.y + w3*a3.y;
    comb.z = w0*a0.z + w1*a1.z + w2*a2.z + w3*a3.z;
    comb.w = w0*a0.w + w1*a1.w + w2*a2.w + w3*a3.w;
    ((float4*)g_pctx)[(size_t)idx * (DM / 4) + tid] = comb;
}

// ============================================================================
// Kernel 3: combine 16 CTA-partials per batch + apply W_v.
// 16 blocks x 512 threads; 4 batches per block.
// ============================================================================
__global__ __launch_bounds__(512) void finish_kernel(
    const float* __restrict__ Wv,
    float*       __restrict__ out)
{
    __shared__ float4 ctxs[4][DM / 4];
    __shared__ float  wsm[4][NPART];

    const int tid = threadIdx.x;
    const int b0  = blockIdx.x * 4;

    if (tid < 4) {
        const int b = b0 + tid;
        float mg = -INFINITY;
        #pragma unroll
        for (int i = 0; i < NPART; i++) mg = fmaxf(mg, g_m[b * NPART + i]);
        float L = 0.f;
        float tmp[NPART];
        #pragma unroll
        for (int i = 0; i < NPART; i++) {
            float w = __expf(g_m[b * NPART + i] - mg);
            tmp[i] = w;
            L += w * g_l[b * NPART + i];
        }
        const float invL = 1.0f / L;
        #pragma unroll
        for (int i = 0; i < NPART; i++) wsm[tid][i] = tmp[i] * invL;
    }
    __syncthreads();

    const int bl = tid >> 7;   // 0..3 batch-local
    const int j  = tid & 127;  // float4 column
    float4 acc = make_float4(0.f, 0.f, 0.f, 0.f);
    const float4* pc = (const float4*)g_pctx
                     + (size_t)(b0 + bl) * NPART * (DM / 4) + j;
    #pragma unroll
    for (int sp = 0; sp < NPART; sp++) {
        const float4 v = pc[(size_t)sp * (DM / 4)];
        const float  w = wsm[bl][sp];
        acc.x += w * v.x; acc.y += w * v.y; acc.z += w * v.z; acc.w += w * v.w;
    }
    ctxs[bl][j] = acc;
    __syncthreads();

    // context[b,v] = sum_d ctx_emb[b,d] * Wv[v,d]
    float s = 0.f;
    const float4* wv = (const float4*)Wv + (size_t)j * (DM / 4);
    #pragma unroll 8
    for (int d = 0; d < DM / 4; d++) {
        const float4 w4 = wv[d];
        const float4 cx = ctxs[bl][d];
        s += w4.x * cx.x + w4.y * cx.y + w4.z * cx.z + w4.w * cx.w;
    }
    out[(size_t)(b0 + bl) * DV + j] = s;
}

// ============================================================================
extern "C" void kernel_launch(void* const* d_in, const int* in_sizes, int n_in,
                              void* d_out, int out_size)
{
    const float* query = (const float*)d_in[0];   // [64, 512]
    const float* embs  = (const float*)d_in[1];   // [64, 32, 256, 512]
    const float* Wq    = (const float*)d_in[2];   // [128, 512]
    const float* Wk    = (const float*)d_in[3];   // [128, 512]
    const float* Wv    = (const float*)d_in[4];   // [128, 512]
    const float* lags  = (const float*)d_in[5];   // [256]
    const float* gates = (const float*)d_in[6];   // [256]
    const void*  ml    = (n_in > 7) ? d_in[7] : nullptr;

    prep_kernel<<<NB, 512>>>(query, Wq, Wk, lags, gates, ml);
    main_kernel<<<dim3(CPB, NB), 128>>>(embs);
    finish_kernel<<<16, 512>>>(Wv, (float*)d_out);
}

// round 6
// speedup vs baseline: 1.2953x; 1.2953x over previous
#include <cuda_runtime.h>
#include <cstdint>
#include <math.h>

#define NB 64
#define LOOKBACK 32
#define NS 256
#define DM 512
#define DK 128
#define DV 128
#define WST 8                  // stocks per warp in main kernel
#define CPB (NS / (4 * WST))   // CTAs per batch in main = 8
#define NPART CPB              // 8 CTA-partials per batch

// ---- scratch (device globals: allocation-free) ----
__device__ float  g_upart[NB * 4 * DM];     // 4 partial u slices per batch
__device__ float4 g_stock[NS];              // {alpha, gate, lag_floor, lag_ceil}
__device__ float  g_pctx[NB * NPART * DM];  // CTA partial contexts (unnormalized)
__device__ float  g_m[NB * NPART];          // CTA running max
__device__ float  g_l[NB * NPART];          // CTA running sum
__device__ unsigned int g_cnt[NB];          // arrival counters (zeroed in prep)

__device__ __forceinline__ float sigmoidf_(float x) {
    return 1.0f / (1.0f + __expf(-x));
}

__device__ __forceinline__ void cp16(void* smem_dst, const void* gmem_src) {
    unsigned int d = (unsigned int)__cvta_generic_to_shared(smem_dst);
    asm volatile("cp.async.cg.shared.global [%0], [%1], 16;\n"
                 :: "r"(d), "l"(gmem_src) : "memory");
}
__device__ __forceinline__ void cp_commit() {
    asm volatile("cp.async.commit_group;\n" ::: "memory");
}
template <int N>
__device__ __forceinline__ void cp_wait() {
    asm volatile("cp.async.wait_group %0;\n" :: "n"(N) : "memory");
}

// ============================================================================
// Kernel 1: prep. grid (4, NB) x 256 threads. CTA (g, b) computes
// q[b, g*32 .. g*32+32) and the partial u from those 32 k's into g_upart.
// ============================================================================
__global__ __launch_bounds__(256) void prep_kernel(
    const float* __restrict__ query,
    const float* __restrict__ Wq,
    const float* __restrict__ Wk,
    const float* __restrict__ lags,
    const float* __restrict__ gates,
    const void*  __restrict__ mlraw)
{
    __shared__ float  qs[DM];
    __shared__ float  qks[32];
    __shared__ float4 sred[2][DM / 4];

    const int tid = threadIdx.x;    // 0..255
    const int g   = blockIdx.x;     // 0..3 k-slice
    const int b   = blockIdx.y;     // batch

    if (g == 0 && tid == 0) g_cnt[b] = 0u;

    // per-stock meta (one CTA)
    if (g == 0 && b == 0) {
        float ml = 16.0f;
        if (mlraw != nullptr) {
            int   iv = ((const int*)mlraw)[0];
            float fv = ((const float*)mlraw)[0];
            ml = (iv > 0 && iv <= 65536) ? (float)iv : fv;
        }
        float lag = sigmoidf_(lags[tid]) * ml;
        int ifl = min(max((int)floorf(lag), 0), LOOKBACK - 1);
        int icl = min(max((int)ceilf(lag),  0), LOOKBACK - 1);
        float alpha = lag - (float)ifl;
        float gate  = sigmoidf_(gates[tid]);
        g_stock[tid] = make_float4(alpha, gate, (float)ifl, (float)icl);
    }

    qs[tid]       = query[(size_t)b * DM + tid];
    qs[tid + 256] = query[(size_t)b * DM + tid + 256];
    __syncthreads();

    // ---- stage A: q[k] for k in this CTA's 32-slice (warp-per-k, 4 rounds) ----
    const int wid  = tid >> 5;     // 0..7
    const int lane = tid & 31;
    #pragma unroll
    for (int r = 0; r < 4; r++) {
        const int kl = r * 8 + wid;
        const int k  = g * 32 + kl;
        float acc = 0.f;
        #pragma unroll
        for (int i = 0; i < 16; i++)
            acc = fmaf(Wq[(size_t)k * DM + i * 32 + lane], qs[i * 32 + lane], acc);
        #pragma unroll
        for (int off = 16; off; off >>= 1)
            acc += __shfl_xor_sync(0xffffffffu, acc, off);
        if (lane == 0) qks[kl] = acc;
    }
    __syncthreads();

    // ---- stage B: partial u over this CTA's 32 k's, K split 2 ways ----
    const int col  = tid & 127;    // float4 column
    const int half = tid >> 7;     // 0..1
    float4 acc = make_float4(0.f, 0.f, 0.f, 0.f);
    const float4* wkb = (const float4*)Wk + (size_t)(g * 32 + half * 16) * (DM / 4) + col;
    #pragma unroll
    for (int kk = 0; kk < 16; kk++) {
        const float  s = qks[half * 16 + kk];
        const float4 w = wkb[(size_t)kk * (DM / 4)];
        acc.x = fmaf(s, w.x, acc.x); acc.y = fmaf(s, w.y, acc.y);
        acc.z = fmaf(s, w.z, acc.z); acc.w = fmaf(s, w.w, acc.w);
    }
    sred[half][col] = acc;
    __syncthreads();

    if (tid < 128) {
        const float inv = 0.08838834764831845f;  // 1/sqrt(128)
        const float4 a = sred[0][tid], c = sred[1][tid];
        float4 r;
        r.x = (a.x + c.x) * inv; r.y = (a.y + c.y) * inv;
        r.z = (a.z + c.z) * inv; r.w = (a.w + c.w) * inv;
        ((float4*)g_upart)[((size_t)b * 4 + g) * (DM / 4) + tid] = r;
    }
}

// ============================================================================
// Kernel 2: main + fused finish. grid (CPB, NB) x 128 threads.
// Depth-3 cp.async pipeline; warp-autonomous online softmax; CTA combine;
// last CTA per batch does the split-combine + W_v epilogue.
// ============================================================================
__global__ __launch_bounds__(128) void main_kernel(
    const float* __restrict__ embs,
    const float* __restrict__ Wv,
    float*       __restrict__ out)
{
    __shared__ float4 pool[3 * 4 * 2 * (DM / 4)];   // 48 KB exactly (pipeline ring)

    const int tid  = threadIdx.x;
    const int lane = tid & 31;
    const int wid  = tid >> 5;
    const int b    = blockIdx.y;
    const int sp   = blockIdx.x;
    const int s0   = (sp * 4 + wid) * WST;

    const float4* base = (const float4*)embs + (size_t)b * LOOKBACK * NS * (DM / 4);

    // u[b] = sum of 4 partial slices
    const float4* up = (const float4*)g_upart + (size_t)b * 4 * (DM / 4);
    float4 u0, u1, u2, u3;
    {
        float4 t0 = up[lane],            t1 = up[128 + lane];
        float4 t2 = up[256 + lane],      t3 = up[384 + lane];
        u0 = make_float4(t0.x+t1.x+t2.x+t3.x, t0.y+t1.y+t2.y+t3.y,
                         t0.z+t1.z+t2.z+t3.z, t0.w+t1.w+t2.w+t3.w);
        t0 = up[32+lane]; t1 = up[160+lane]; t2 = up[288+lane]; t3 = up[416+lane];
        u1 = make_float4(t0.x+t1.x+t2.x+t3.x, t0.y+t1.y+t2.y+t3.y,
                         t0.z+t1.z+t2.z+t3.z, t0.w+t1.w+t2.w+t3.w);
        t0 = up[64+lane]; t1 = up[192+lane]; t2 = up[320+lane]; t3 = up[448+lane];
        u2 = make_float4(t0.x+t1.x+t2.x+t3.x, t0.y+t1.y+t2.y+t3.y,
                         t0.z+t1.z+t2.z+t3.z, t0.w+t1.w+t2.w+t3.w);
        t0 = up[96+lane]; t1 = up[224+lane]; t2 = up[352+lane]; t3 = up[480+lane];
        u3 = make_float4(t0.x+t1.x+t2.x+t3.x, t0.y+t1.y+t2.y+t3.y,
                         t0.z+t1.z+t2.z+t3.z, t0.w+t1.w+t2.w+t3.w);
    }

    // stage pointer: ((st*4 + wid)*2 + fc) * 128
    auto stg = [&](int st, int fc) -> float4* {
        return pool + ((size_t)((st * 4 + wid) * 2 + fc)) * (DM / 4);
    };
    auto issue = [&](int i) {
        const int s = s0 + i;
        const float4 mt = g_stock[s];
        const float4* rf = base + ((int)mt.z * NS + s) * (DM / 4);
        const float4* rc = base + ((int)mt.w * NS + s) * (DM / 4);
        float4* df = stg(i % 3, 0);
        float4* dc = stg(i % 3, 1);
        #pragma unroll
        for (int r = 0; r < 4; r++) {
            cp16(df + r * 32 + lane, rf + r * 32 + lane);
            cp16(dc + r * 32 + lane, rc + r * 32 + lane);
        }
        cp_commit();
    };

    issue(0); issue(1); issue(2);

    float  m = -INFINITY, l = 0.f;
    float4 x0 = make_float4(0.f,0.f,0.f,0.f), x1 = x0, x2 = x0, x3 = x0;

    #pragma unroll
    for (int i = 0; i < WST; i++) {
        if (i <= WST - 3)      cp_wait<2>();
        else if (i == WST - 2) cp_wait<1>();
        else                   cp_wait<0>();

        const float4* df = stg(i % 3, 0);
        const float4* dc = stg(i % 3, 1);
        float4 f0 = df[lane], f1 = df[32+lane], f2 = df[64+lane], f3 = df[96+lane];
        float4 c0 = dc[lane], c1 = dc[32+lane], c2 = dc[64+lane], c3 = dc[96+lane];

        if (i + 3 < WST) issue(i + 3);

        const float4 mt = g_stock[s0 + i];
        const float a = mt.x, gt = mt.y, oma = 1.0f - mt.x;

        f0.x = oma*f0.x + a*c0.x; f0.y = oma*f0.y + a*c0.y; f0.z = oma*f0.z + a*c0.z; f0.w = oma*f0.w + a*c0.w;
        f1.x = oma*f1.x + a*c1.x; f1.y = oma*f1.y + a*c1.y; f1.z = oma*f1.z + a*c1.z; f1.w = oma*f1.w + a*c1.w;
        f2.x = oma*f2.x + a*c2.x; f2.y = oma*f2.y + a*c2.y; f2.z = oma*f2.z + a*c2.z; f2.w = oma*f2.w + a*c2.w;
        f3.x = oma*f3.x + a*c3.x; f3.y = oma*f3.y + a*c3.y; f3.z = oma*f3.z + a*c3.z; f3.w = oma*f3.w + a*c3.w;

        float p0 = f0.x*u0.x + f0.y*u0.y + f0.z*u0.z + f0.w*u0.w;
        float p1 = f1.x*u1.x + f1.y*u1.y + f1.z*u1.z + f1.w*u1.w;
        float p2 = f2.x*u2.x + f2.y*u2.y + f2.z*u2.z + f2.w*u2.w;
        float p3 = f3.x*u3.x + f3.y*u3.y + f3.z*u3.z + f3.w*u3.w;
        float part = (p0 + p1) + (p2 + p3);
        #pragma unroll
        for (int off = 16; off; off >>= 1)
            part += __shfl_xor_sync(0xffffffffu, part, off);
        const float score = part * gt;   // 1/sqrt(dk) folded into u

        const float mnew = fmaxf(m, score);
        const float corr = __expf(m - mnew);
        const float p    = __expf(score - mnew);
        l = l * corr + p;
        x0.x = x0.x*corr + p*f0.x; x0.y = x0.y*corr + p*f0.y; x0.z = x0.z*corr + p*f0.z; x0.w = x0.w*corr + p*f0.w;
        x1.x = x1.x*corr + p*f1.x; x1.y = x1.y*corr + p*f1.y; x1.z = x1.z*corr + p*f1.z; x1.w = x1.w*corr + p*f1.w;
        x2.x = x2.x*corr + p*f2.x; x2.y = x2.y*corr + p*f2.y; x2.z = x2.z*corr + p*f2.z; x2.w = x2.w*corr + p*f2.w;
        x3.x = x3.x*corr + p*f3.x; x3.y = x3.y*corr + p*f3.y; x3.z = x3.z*corr + p*f3.z; x3.w = x3.w*corr + p*f3.w;
        m = mnew;
    }

    // ---- CTA combine of 4 warp partials (reuse pool) ----
    __syncthreads();                       // pipeline fully drained
    float4* sctx = pool;                   // [0..511]
    float*  smf  = (float*)(pool + 512);   // [0..3]=m, [4..7]=l
    unsigned int* slast = (unsigned int*)(pool + 513);
    if (lane == 0) { smf[wid] = m; smf[4 + wid] = l; }
    sctx[wid * 128 + lane]      = x0;
    sctx[wid * 128 + 32 + lane] = x1;
    sctx[wid * 128 + 64 + lane] = x2;
    sctx[wid * 128 + 96 + lane] = x3;
    __syncthreads();

    const float m0 = smf[0], m1 = smf[1], m2 = smf[2], m3 = smf[3];
    const float mg = fmaxf(fmaxf(m0, m1), fmaxf(m2, m3));
    const float w0 = __expf(m0 - mg), w1 = __expf(m1 - mg);
    const float w2 = __expf(m2 - mg), w3 = __expf(m3 - mg);

    const int idx = b * NPART + sp;
    if (tid == 0) {
        g_m[idx] = mg;
        g_l[idx] = w0 * smf[4] + w1 * smf[5] + w2 * smf[6] + w3 * smf[7];
    }
    const float4 a0 = sctx[tid], a1 = sctx[128 + tid], a2 = sctx[256 + tid], a3 = sctx[384 + tid];
    float4 comb;
    comb.x = w0*a0.x + w1*a1.x + w2*a2.x + w3*a3.x;
    comb.y = w0*a0.y + w1*a1.y + w2*a2.y + w3*a3.y;
    comb.z = w0*a0.z + w1*a1.z + w2*a2.z + w3*a3.z;
    comb.w = w0*a0.w + w1*a1.w + w2*a2.w + w3*a3.w;
    ((float4*)g_pctx)[(size_t)idx * (DM / 4) + tid] = comb;

    // ---- fused finish: last CTA of batch b combines + applies W_v ----
    __threadfence();
    __syncthreads();                 // everyone's comb read of sctx done
    if (tid == 0) *slast = atomicAdd(&g_cnt[b], 1u);
    __syncthreads();
    const bool last = (*slast == NPART - 1);
    if (last) {
        // split-combine weights (redundant per thread; NPART=8 small)
        float mv[NPART];
        float mgf = -INFINITY;
        #pragma unroll
        for (int i = 0; i < NPART; i++) { mv[i] = g_m[b * NPART + i]; mgf = fmaxf(mgf, mv[i]); }
        float L = 0.f;
        float ws[NPART];
        #pragma unroll
        for (int i = 0; i < NPART; i++) {
            const float w = __expf(mv[i] - mgf);
            ws[i] = w;
            L += w * g_l[b * NPART + i];
        }
        const float invL = 1.0f / L;

        float4 acc = make_float4(0.f, 0.f, 0.f, 0.f);
        const float4* pc = (const float4*)g_pctx + (size_t)b * NPART * (DM / 4) + tid;
        #pragma unroll
        for (int i = 0; i < NPART; i++) {
            const float4 v = pc[(size_t)i * (DM / 4)];
            const float  w = ws[i] * invL;
            acc.x += w * v.x; acc.y += w * v.y; acc.z += w * v.z; acc.w += w * v.w;
        }
        __syncthreads();             // done with sctx/slast region before reuse
        pool[tid] = acc;             // ctx_emb slice
        __syncthreads();

        // context[b, v] = sum_d ctx_emb[d] * Wv[v, d]   (thread v = tid)
        float s0a = 0.f, s1a = 0.f, s2a = 0.f, s3a = 0.f;
        const float4* wv = (const float4*)Wv + (size_t)tid * (DM / 4);
        #pragma unroll 8
        for (int d = 0; d < DM / 4; d += 4) {
            const float4 wa = wv[d],     ca = pool[d];
            const float4 wb = wv[d + 1], cb = pool[d + 1];
            const float4 wc = wv[d + 2], cc = pool[d + 2];
            const float4 wd = wv[d + 3], cd = pool[d + 3];
            s0a += wa.x*ca.x + wa.y*ca.y + wa.z*ca.z + wa.w*ca.w;
            s1a += wb.x*cb.x + wb.y*cb.y + wb.z*cb.z + wb.w*cb.w;
            s2a += wc.x*cc.x + wc.y*cc.y + wc.z*cc.z + wc.w*cc.w;
            s3a += wd.x*cd.x + wd.y*cd.y + wd.z*cd.z + wd.w*cd.w;
        }
        out[(size_t)b * DV + tid] = (s0a + s1a) + (s2a + s3a);
    }
}

// ============================================================================
extern "C" void kernel_launch(void* const* d_in, const int* in_sizes, int n_in,
                              void* d_out, int out_size)
{
    const float* query = (const float*)d_in[0];   // [64, 512]
    const float* embs  = (const float*)d_in[1];   // [64, 32, 256, 512]
    const float* Wq    = (const float*)d_in[2];   // [128, 512]
    const float* Wk    = (const float*)d_in[3];   // [128, 512]
    const float* Wv    = (const float*)d_in[4];   // [128, 512]
    const float* lags  = (const float*)d_in[5];   // [256]
    const float* gates = (const float*)d_in[6];   // [256]
    const void*  ml    = (n_in > 7) ? d_in[7] : nullptr;

    prep_kernel<<<dim3(4, NB), 256>>>(query, Wq, Wk, lags, gates, ml);
    main_kernel<<<dim3(CPB, NB), 128>>>(embs, Wv, (float*)d_out);
}